// round 15
// baseline (speedup 1.0000x reference)
#include <cuda_runtime.h>
#include <cuda_fp16.h>
#include <math.h>
#include <cstdint>

#define B_   128
#define T_   20
#define E_   512
#define H_   512
#define V_   32000
#define G4H  2048   // 4*H
#define K3_  1536   // 3-term split-extended K
#define NSPLIT 8

// ---------------- scratch (static device globals; IN-KERNEL access only) ----------------
__device__ float g_Gx[T_ * B_ * G4H];
__device__ float g_hs[T_ * B_ * H_];
__device__ float g_c[B_ * H_];
__device__ float g_part[NSPLIT * G4H * B_];
__device__ int   g_sem[16];             // per-mtile split-K semaphore (self-resetting)
__device__ int   g_nt[T_];
__device__ int   g_off[T_ + 1];
__device__ int   g_local[T_ * B_];
__device__ int   g_rowmap[T_ * B_];

__device__ __align__(16) __half g_X2[2560u * K3_];
__device__ __align__(16) __half g_Wih[G4H * K3_];
__device__ __align__(16) __half g_Whh[G4H * K3_];      // GATE-INTERLEAVED rows
__device__ __align__(16) __half g_h2[2][B_ * K3_];
__device__ __align__(16) __half g_Ah[1664u * 512u];
__device__ __align__(16) __half g_Bh[32000u * 512u];

// ---------------- PTX helpers ----------------
__device__ __forceinline__ uint32_t smem_u32(const void* p) {
    uint32_t a;
    asm("{ .reg .u64 t; cvta.to.shared.u64 t, %1; cvt.u32.u64 %0, t; }" : "=r"(a) : "l"(p));
    return a;
}
__device__ __forceinline__ void cp_async16(uint32_t saddr, const void* g) {
    asm volatile("cp.async.cg.shared.global [%0], [%1], 16;" :: "r"(saddr), "l"(g));
}
__device__ __forceinline__ void ldsm_x4(uint32_t* r, uint32_t addr) {
    asm volatile("ldmatrix.sync.aligned.m8n8.x4.shared.b16 {%0,%1,%2,%3}, [%4];"
        : "=r"(r[0]), "=r"(r[1]), "=r"(r[2]), "=r"(r[3]) : "r"(addr));
}
__device__ __forceinline__ void mma_fp16(float* d, const uint32_t* a, const uint32_t* b) {
    asm volatile("mma.sync.aligned.m16n8k16.row.col.f32.f16.f16.f32 "
        "{%0,%1,%2,%3}, {%4,%5,%6,%7}, {%8,%9}, {%0,%1,%2,%3};"
        : "+f"(d[0]), "+f"(d[1]), "+f"(d[2]), "+f"(d[3])
        : "r"(a[0]), "r"(a[1]), "r"(a[2]), "r"(a[3]), "r"(b[0]), "r"(b[1]));
}

// ---------------- pack-index machinery ----------------
__global__ void count_kernel(const int* __restrict__ lengths) {
    int t = blockIdx.x, b = threadIdx.x;
    int pred = lengths[b] > t;
    unsigned m = __ballot_sync(0xffffffffu, pred);
    int lane = b & 31, w = b >> 5;
    __shared__ int ws[4];
    if (lane == 0) ws[w] = __popc(m);
    __syncthreads();
    int prefix = 0;
#pragma unroll
    for (int i = 0; i < 4; i++) if (i < w) prefix += ws[i];
    g_local[t * B_ + b] = prefix + __popc(m & ((1u << lane) - 1u));
    if (b == 0) {
        int tot = 0;
#pragma unroll
        for (int i = 0; i < 4; i++) tot += ws[i];
        g_nt[t] = tot;
    }
}

__global__ void offset_kernel() {
    int o = 0;
    for (int t = 0; t < T_; t++) { g_off[t] = o; o += g_nt[t]; }
    g_off[T_] = o;
}

__global__ void scatter_kernel(const int* __restrict__ lengths) {
    int idx = blockIdx.x * 256 + threadIdx.x;
    if (idx >= T_ * B_) return;
    int t = idx >> 7, b = idx & 127;
    if (lengths[b] > t) g_rowmap[g_off[t] + g_local[idx]] = idx;
}

// ---------------- converters ----------------
// Wih: logical rows.  Whh: gate-interleaved rows n' = mt*128 + g*32 + jj.
__global__ void convert_w_both(const float2* __restrict__ w_ih,
                               const float2* __restrict__ w_hh) {
    int idx = blockIdx.x * 256 + threadIdx.x;     // 2 * (2048*512)/2
    int half_sel = idx >= (G4H * 256);
    int i = idx - half_sel * (G4H * 256);
    int n = i >> 8, k2 = i & 255;
    const float2* w = half_sel ? w_hh : w_ih;
    float2 v = w[i];
    __half2 hi = __floats2half2_rn(v.x, v.y);
    __half2 lo = __floats2half2_rn(v.x - __low2float(hi), v.y - __high2float(hi));
    int nrow;
    __half* dst;
    if (half_sel) {
        int g = n >> 9, j = n & 511;
        nrow = (j >> 5) * 128 + g * 32 + (j & 31);   // permuted
        dst = g_Whh;
    } else {
        nrow = n;
        dst = g_Wih;
    }
    __half2* base = (__half2*)(dst + (size_t)nrow * K3_ + 2 * k2);
    base[0] = hi; base[256] = hi; base[512] = lo;
}

__global__ void convert_x2(const float* __restrict__ features,
                           const int*   __restrict__ captions,
                           const float* __restrict__ embed_w) {
    int idx = blockIdx.x * 256 + threadIdx.x;
    int r = idx >> 8, k2 = idx & 255;
    int t = r >> 7, b = r & 127;
    float2 v;
    if (t == 0) v = ((const float2*)features)[b * 256 + k2];
    else        v = ((const float2*)embed_w)[(size_t)captions[b * T_ + (t - 1)] * 256 + k2];
    __half2 hi = __floats2half2_rn(v.x, v.y);
    __half2 lo = __floats2half2_rn(v.x - __low2float(hi), v.y - __high2float(hi));
    __half2* base = (__half2*)(g_X2 + (size_t)r * K3_ + 2 * k2);
    base[0] = hi; base[256] = lo; base[512] = hi;
}

__global__ void init_h2(const float* __restrict__ h0) {
    int idx = blockIdx.x * 256 + threadIdx.x;
    int b = idx >> 9, k = idx & 511;
    float v = h0[idx];
    __half hi = __float2half(v);
    __half lo = __float2half(v - __half2float(hi));
    size_t base = (size_t)b * K3_ + k;
    g_h2[0][base] = hi; g_h2[0][base + 512] = lo; g_h2[0][base + 1024] = hi;
}

__global__ void convert_Bout(const float4* __restrict__ lin_w4) {
    int idx = blockIdx.x * 256 + threadIdx.x;
    float4 a = lin_w4[2 * idx], b = lin_w4[2 * idx + 1];
    __half2 h0 = __floats2half2_rn(a.x, a.y);
    __half2 h1 = __floats2half2_rn(a.z, a.w);
    __half2 h2 = __floats2half2_rn(b.x, b.y);
    __half2 h3 = __floats2half2_rn(b.z, b.w);
    uint4 o = {*(uint32_t*)&h0, *(uint32_t*)&h1, *(uint32_t*)&h2, *(uint32_t*)&h3};
    ((uint4*)g_Bh)[idx] = o;
}

__global__ void convert_Aout() {
    int idx = blockIdx.x * 256 + threadIdx.x;
    int m = idx >> 6, k8 = (idx & 63) * 8;
    int nr = g_off[T_];
    int src = (m < nr) ? g_rowmap[m] : 0;
    const float4* p = (const float4*)(g_hs + (size_t)src * 512 + k8);
    float4 a = p[0], b = p[1];
    __half2 h0 = __floats2half2_rn(a.x, a.y);
    __half2 h1 = __floats2half2_rn(a.z, a.w);
    __half2 h2 = __floats2half2_rn(b.x, b.y);
    __half2 h3 = __floats2half2_rn(b.z, b.w);
    uint4 o = {*(uint32_t*)&h0, *(uint32_t*)&h1, *(uint32_t*)&h2, *(uint32_t*)&h3};
    *(uint4*)(g_Ah + (size_t)m * 512 + k8) = o;
}

// ---------------- shared template constants ----------------
#define RS_      144
#define STAGE_   36864

// ---------------- gx GEMM: 2-stage, 2 CTAs/SM (proven R14) ----------------
__global__ void __launch_bounds__(256, 2) gx_mma(const float* __restrict__ b_ih,
                                                 const float* __restrict__ b_hh) {
    extern __shared__ char smem[];
    uint32_t sb = smem_u32(smem);
    int tid = threadIdx.x, lane = tid & 31, wid = tid >> 5;
    int n0 = blockIdx.x * 128, m0 = blockIdx.y * 128;
    int wm = (wid >> 2) * 64, wn = (wid & 3) * 32;
    float acc[4][4][4] = {};

#define GX_LOAD(s, kc) do { \
        uint32_t base_ = sb + (s) * STAGE_; \
        int k0_ = (kc) * 64; \
        for (int i = tid; i < 1024; i += 256) { \
            int r_ = i >> 3, c_ = i & 7; \
            cp_async16(base_ + r_ * RS_ + c_ * 16, \
                       g_X2 + (size_t)(m0 + r_) * K3_ + k0_ + c_ * 8); \
            cp_async16(base_ + 18432 + r_ * RS_ + c_ * 16, \
                       g_Wih + (size_t)(n0 + r_) * K3_ + k0_ + c_ * 8); \
        } \
        asm volatile("cp.async.commit_group;" ::: "memory"); \
    } while (0)

    GX_LOAD(0, 0);
    GX_LOAD(1, 1);
    for (int kc = 0; kc < 24; kc++) {
        asm volatile("cp.async.wait_group 1;" ::: "memory");
        __syncthreads();
        int s = kc & 1;
        uint32_t sA = sb + s * STAGE_;
        uint32_t sB = sA + 18432;
        uint32_t aA = sA + (uint32_t)(wm + (lane & 15)) * RS_ + ((lane >> 4) << 4);
        uint32_t aB = sB + (uint32_t)(wn + (lane & 7) + ((lane & 16) >> 1)) * RS_ + ((lane & 8) << 1);
#pragma unroll
        for (int st = 0; st < 4; st++) {
            uint32_t af[4][4], bfr[2][4];
#pragma unroll
            for (int ta = 0; ta < 4; ta++) ldsm_x4(af[ta], aA + ta * (16 * RS_) + st * 32);
#pragma unroll
            for (int tb = 0; tb < 2; tb++) ldsm_x4(bfr[tb], aB + tb * (16 * RS_) + st * 32);
#pragma unroll
            for (int ta = 0; ta < 4; ta++)
#pragma unroll
                for (int tn = 0; tn < 4; tn++)
                    mma_fp16(acc[ta][tn], af[ta], &bfr[tn >> 1][(tn & 1) * 2]);
        }
        __syncthreads();
        if (kc + 2 < 24) GX_LOAD(s, kc + 2);
        else asm volatile("cp.async.commit_group;" ::: "memory");
    }
#undef GX_LOAD

    int g = lane >> 2, tc2 = (lane & 3) * 2;
#pragma unroll
    for (int ta = 0; ta < 4; ta++) {
        int j0 = m0 + wm + ta * 16 + g;
#pragma unroll
        for (int tn = 0; tn < 4; tn++) {
            int col = n0 + wn + tn * 8 + tc2;
            float2 bi = {b_ih[col] + b_hh[col], b_ih[col + 1] + b_hh[col + 1]};
            float2 o0 = {acc[ta][tn][0] + bi.x, acc[ta][tn][1] + bi.y};
            float2 o1 = {acc[ta][tn][2] + bi.x, acc[ta][tn][3] + bi.y};
            *(float2*)&g_Gx[(size_t)j0 * G4H + col] = o0;
            *(float2*)&g_Gx[(size_t)(j0 + 8) * G4H + col] = o1;
        }
    }
}

// ---------------- recurrence GEMM + fused split-K cell epilogue ----------------
__device__ __forceinline__ float sigmoidf_(float x) { return 1.0f / (1.0f + expf(-x)); }

__global__ void __launch_bounds__(256, 1) rec_gemm(int t, const float* __restrict__ c0) {
    extern __shared__ char smem[];
    uint32_t sb = smem_u32(smem);
    int tid = threadIdx.x, lane = tid & 31, wid = tid >> 5;
    int split = blockIdx.x;
    int mt = blockIdx.y;                 // 0..15
    int m0 = mt * 128;                   // permuted Whh rows
    const __half* hin = g_h2[t & 1];
    int wm = (wid >> 2) * 64, wn = (wid & 3) * 32;

    float acc[4][4][4] = {};

#define REC_LOAD(s, kc) do { \
        uint32_t base_ = sb + (s) * STAGE_; \
        int k0_ = (split * 3 + (kc)) * 64; \
        for (int i = tid; i < 1024; i += 256) { \
            int r_ = i >> 3, c_ = i & 7; \
            cp_async16(base_ + r_ * RS_ + c_ * 16, \
                       g_Whh + (size_t)(m0 + r_) * K3_ + k0_ + c_ * 8); \
            cp_async16(base_ + 18432 + r_ * RS_ + c_ * 16, \
                       hin + (size_t)r_ * K3_ + k0_ + c_ * 8); \
        } \
        asm volatile("cp.async.commit_group;" ::: "memory"); \
    } while (0)

    REC_LOAD(0, 0);
    REC_LOAD(1, 1);

    for (int kc = 0; kc < 3; kc++) {
        asm volatile("cp.async.wait_group 1;" ::: "memory");
        __syncthreads();
        int s = kc & 1;
        uint32_t sA = sb + s * STAGE_;
        uint32_t sB = sA + 18432;
        uint32_t aA = sA + (uint32_t)(wm + (lane & 15)) * RS_ + ((lane >> 4) << 4);
        uint32_t aB = sB + (uint32_t)(wn + (lane & 7) + ((lane & 16) >> 1)) * RS_ + ((lane & 8) << 1);
#pragma unroll
        for (int st = 0; st < 4; st++) {
            uint32_t af[4][4], bfr[2][4];
#pragma unroll
            for (int ta = 0; ta < 4; ta++) ldsm_x4(af[ta], aA + ta * (16 * RS_) + st * 32);
#pragma unroll
            for (int tb = 0; tb < 2; tb++) ldsm_x4(bfr[tb], aB + tb * (16 * RS_) + st * 32);
#pragma unroll
            for (int ta = 0; ta < 4; ta++)
#pragma unroll
                for (int tn = 0; tn < 4; tn++)
                    mma_fp16(acc[ta][tn], af[ta], &bfr[tn >> 1][(tn & 1) * 2]);
        }
        __syncthreads();
        if (kc + 2 < 3) REC_LOAD(s, kc + 2);
        else asm volatile("cp.async.commit_group;" ::: "memory");
    }
#undef REC_LOAD

    // write partials (n' local rows within this mtile)
    {
        float* part = g_part + (size_t)split * G4H * B_;
        int g = lane >> 2, tc2 = (lane & 3) * 2;
#pragma unroll
        for (int ta = 0; ta < 4; ta++) {
            int j0 = m0 + wm + ta * 16 + g;
            int j1 = j0 + 8;
#pragma unroll
            for (int tn = 0; tn < 4; tn++) {
                int col = wn + tn * 8 + tc2;
                float2 o0 = {acc[ta][tn][0], acc[ta][tn][1]};
                float2 o1 = {acc[ta][tn][2], acc[ta][tn][3]};
                *(float2*)&part[(size_t)j0 * B_ + col] = o0;
                *(float2*)&part[(size_t)j1 * B_ + col] = o1;
            }
        }
    }

    // split-K semaphore: last CTA for this mtile runs the cell for its 32 j-columns
    __threadfence();
    __syncthreads();
    __shared__ int is_last;
    if (tid == 0) is_last = (atomicAdd(&g_sem[mt], 1) == NSPLIT - 1);
    __syncthreads();
    if (!is_last) return;

    __half* hout = g_h2[(t + 1) & 1];
    int b = tid & 127, half = tid >> 7;
#pragma unroll
    for (int i = 0; i < 16; i++) {
        int jj = half * 16 + i;
        int j = mt * 32 + jj;
        const float* gxr = g_Gx + (size_t)(t * B_ + b) * G4H;
        float gate[4];
#pragma unroll
        for (int g = 0; g < 4; g++) {
            float s = gxr[g * 512 + j];
            size_t off = (size_t)(m0 + g * 32 + jj) * B_ + b;
#pragma unroll
            for (int sp = 0; sp < NSPLIT; sp++)
                s += g_part[(size_t)sp * G4H * B_ + off];
            gate[g] = s;
        }
        float cp = (t == 0) ? c0[b * 512 + j] : g_c[j * 128 + b];
        float cn = sigmoidf_(gate[1]) * cp + sigmoidf_(gate[0]) * tanhf(gate[2]);
        float h = sigmoidf_(gate[3]) * tanhf(cn);
        g_c[j * 128 + b] = cn;
        g_hs[(size_t)t * B_ * H_ + b * 512 + j] = h;
        __half hh = __float2half(h);
        __half hl = __float2half(h - __half2float(hh));
        size_t hb = (size_t)b * K3_ + j;
        hout[hb] = hh; hout[hb + 512] = hl; hout[hb + 1024] = hh;
    }
    __syncthreads();
    if (tid == 0) g_sem[mt] = 0;   // self-reset for next step / graph replay
}

// ---------------- out GEMM: 2-stage, 2 CTAs/SM (proven R13) ----------------
#define NCHUNK_  8

__global__ void __launch_bounds__(256, 2) out_gemm_mma(const float* __restrict__ lin_b,
                                                       float* __restrict__ out, int nrows) {
    extern __shared__ char smem[];
    uint32_t sb = smem_u32(smem);
    int tid = threadIdx.x, lane = tid & 31, wid = tid >> 5;
    int n0 = blockIdx.x * 128, m0 = blockIdx.y * 128;
    int wm = (wid >> 2) * 64, wn = (wid & 3) * 32;

    float acc[4][4][4] = {};

#define LOAD_STAGE(s, kc) do { \
        uint32_t base_ = sb + (s) * STAGE_; \
        int k0_ = (kc) * 64; \
        for (int i = tid; i < 1024; i += 256) { \
            int r_ = i >> 3, c_ = i & 7; \
            cp_async16(base_ + r_ * RS_ + c_ * 16, \
                       g_Ah + (size_t)(m0 + r_) * 512 + k0_ + c_ * 8); \
            cp_async16(base_ + 18432 + r_ * RS_ + c_ * 16, \
                       g_Bh + (size_t)(n0 + r_) * 512 + k0_ + c_ * 8); \
        } \
        asm volatile("cp.async.commit_group;" ::: "memory"); \
    } while (0)

    LOAD_STAGE(0, 0);
    LOAD_STAGE(1, 1);

    for (int kc = 0; kc < NCHUNK_; kc++) {
        asm volatile("cp.async.wait_group 1;" ::: "memory");
        __syncthreads();
        int s = kc & 1;
        uint32_t sA = sb + s * STAGE_;
        uint32_t sB = sA + 18432;
        uint32_t aA = sA + (uint32_t)(wm + (lane & 15)) * RS_ + ((lane >> 4) << 4);
        uint32_t aB = sB + (uint32_t)(wn + (lane & 7) + ((lane & 16) >> 1)) * RS_ + ((lane & 8) << 1);
#pragma unroll
        for (int st = 0; st < 4; st++) {
            uint32_t af[4][4], bfr[2][4];
#pragma unroll
            for (int ta = 0; ta < 4; ta++) ldsm_x4(af[ta], aA + ta * (16 * RS_) + st * 32);
#pragma unroll
            for (int tb = 0; tb < 2; tb++) ldsm_x4(bfr[tb], aB + tb * (16 * RS_) + st * 32);
#pragma unroll
            for (int ta = 0; ta < 4; ta++)
#pragma unroll
                for (int tn = 0; tn < 4; tn++)
                    mma_fp16(acc[ta][tn], af[ta], &bfr[tn >> 1][(tn & 1) * 2]);
        }
        __syncthreads();
        if (kc + 2 < NCHUNK_) {
            LOAD_STAGE(s, kc + 2);
        } else {
            asm volatile("cp.async.commit_group;" ::: "memory");
        }
    }
#undef LOAD_STAGE

    int g = lane >> 2, tc2 = (lane & 3) * 2;
#pragma unroll
    for (int ta = 0; ta < 4; ta++) {
        int j0 = m0 + wm + ta * 16 + g;
        int j1 = j0 + 8;
#pragma unroll
        for (int tn = 0; tn < 4; tn++) {
            int col = n0 + wn + tn * 8 + tc2;
            float2 lb = *(const float2*)&lin_b[col];
            if (j0 < nrows) {
                float2 o = {acc[ta][tn][0] + lb.x, acc[ta][tn][1] + lb.y};
                *(float2*)&out[(size_t)j0 * V_ + col] = o;
            }
            if (j1 < nrows) {
                float2 o = {acc[ta][tn][2] + lb.x, acc[ta][tn][3] + lb.y};
                *(float2*)&out[(size_t)j1 * V_ + col] = o;
            }
        }
    }
}

// ---------------- launch ----------------
extern "C" void kernel_launch(void* const* d_in, const int* in_sizes, int n_in,
                              void* d_out, int out_size) {
    const float* features = (const float*)d_in[0];
    const int*   captions = (const int*)d_in[1];
    const int*   lengths  = (const int*)d_in[2];
    const float* h0       = (const float*)d_in[3];
    const float* c0       = (const float*)d_in[4];
    const float* embed_w  = (const float*)d_in[5];
    const float* w_ih     = (const float*)d_in[6];
    const float* w_hh     = (const float*)d_in[7];
    const float* b_ih     = (const float*)d_in[8];
    const float* b_hh     = (const float*)d_in[9];
    const float* lin_w    = (const float*)d_in[10];
    const float* lin_b    = (const float*)d_in[11];
    float* out = (float*)d_out;
    int nrows = out_size / V_;

    cudaFuncSetAttribute(out_gemm_mma, cudaFuncAttributeMaxDynamicSharedMemorySize,
                         2 * STAGE_);
    cudaFuncSetAttribute(gx_mma, cudaFuncAttributeMaxDynamicSharedMemorySize,
                         2 * STAGE_);
    cudaFuncSetAttribute(rec_gemm, cudaFuncAttributeMaxDynamicSharedMemorySize,
                         2 * STAGE_);

    // pack indices
    count_kernel<<<T_, 128>>>(lengths);
    offset_kernel<<<1, 1>>>();
    scatter_kernel<<<(T_ * B_ + 255) / 256, 256>>>(lengths);

    // operand builds
    convert_Bout<<<(V_ * 512 / 8) / 256, 256>>>((const float4*)lin_w);
    convert_w_both<<<(2 * G4H * 512 / 2) / 256, 256>>>((const float2*)w_ih,
                                                       (const float2*)w_hh);
    convert_x2<<<(2560 * 512 / 2) / 256, 256>>>(features, captions, embed_w);
    init_h2<<<(B_ * 512) / 256, 256>>>(h0);

    // input projection
    gx_mma<<<dim3(G4H / 128, 2560 / 128), 256, 2 * STAGE_>>>(b_ih, b_hh);

    // recurrence: GEMM + fused cell, one launch per step
    for (int t = 0; t < T_; t++)
        rec_gemm<<<dim3(NSPLIT, 16), 256, 2 * STAGE_>>>(t, c0);

    // A operand build
    convert_Aout<<<(1664 * 512 / 8) / 256, 256>>>();

    // logits GEMM
    int mtiles = (nrows + 127) / 128;   // 13
    out_gemm_mma<<<dim3(V_ / 128, mtiles), 256, 2 * STAGE_>>>(lin_b, out, nrows);
}

// round 16
// speedup vs baseline: 3.6899x; 3.6899x over previous
#include <cuda_runtime.h>
#include <cuda_fp16.h>
#include <math.h>
#include <cstdint>

#define B_   128
#define T_   20
#define E_   512
#define H_   512
#define V_   32000
#define G4H  2048   // 4*H
#define K2_  1024   // 2-term split-extended K
#define NSPLIT 8

// ---------------- scratch (static device globals; IN-KERNEL access only) ----------------
__device__ float g_Gx[T_ * B_ * G4H];
__device__ float g_hs[T_ * B_ * H_];
__device__ float g_c[B_ * H_];
__device__ float g_part[NSPLIT * G4H * B_];
__device__ int   g_nt[T_];
__device__ int   g_off[T_ + 1];
__device__ int   g_local[T_ * B_];
__device__ int   g_rowmap[T_ * B_];

__device__ __align__(16) __half g_X2[2560u * K2_];     // [xhi | xlo]
__device__ __align__(16) __half g_Wih[G4H * K2_];      // [whi | whi]
__device__ __align__(16) __half g_Whh[G4H * K2_];      // [whi | whi]
__device__ __align__(16) __half g_h2[2][B_ * K2_];     // ping-pong [hhi | hlo]
__device__ __align__(16) __half g_Ah[1664u * 512u];
__device__ __align__(16) __half g_Bh[32000u * 512u];

// ---------------- PTX helpers ----------------
__device__ __forceinline__ uint32_t smem_u32(const void* p) {
    uint32_t a;
    asm("{ .reg .u64 t; cvta.to.shared.u64 t, %1; cvt.u32.u64 %0, t; }" : "=r"(a) : "l"(p));
    return a;
}
__device__ __forceinline__ void cp_async16(uint32_t saddr, const void* g) {
    asm volatile("cp.async.cg.shared.global [%0], [%1], 16;" :: "r"(saddr), "l"(g));
}
__device__ __forceinline__ void ldsm_x4(uint32_t* r, uint32_t addr) {
    asm volatile("ldmatrix.sync.aligned.m8n8.x4.shared.b16 {%0,%1,%2,%3}, [%4];"
        : "=r"(r[0]), "=r"(r[1]), "=r"(r[2]), "=r"(r[3]) : "r"(addr));
}
__device__ __forceinline__ void mma_fp16(float* d, const uint32_t* a, const uint32_t* b) {
    asm volatile("mma.sync.aligned.m16n8k16.row.col.f32.f16.f16.f32 "
        "{%0,%1,%2,%3}, {%4,%5,%6,%7}, {%8,%9}, {%0,%1,%2,%3};"
        : "+f"(d[0]), "+f"(d[1]), "+f"(d[2]), "+f"(d[3])
        : "r"(a[0]), "r"(a[1]), "r"(a[2]), "r"(a[3]), "r"(b[0]), "r"(b[1]));
}

// ---------------- pack-index machinery ----------------
__global__ void count_kernel(const int* __restrict__ lengths) {
    int t = blockIdx.x, b = threadIdx.x;
    int pred = lengths[b] > t;
    unsigned m = __ballot_sync(0xffffffffu, pred);
    int lane = b & 31, w = b >> 5;
    __shared__ int ws[4];
    if (lane == 0) ws[w] = __popc(m);
    __syncthreads();
    int prefix = 0;
#pragma unroll
    for (int i = 0; i < 4; i++) if (i < w) prefix += ws[i];
    g_local[t * B_ + b] = prefix + __popc(m & ((1u << lane) - 1u));
    if (b == 0) {
        int tot = 0;
#pragma unroll
        for (int i = 0; i < 4; i++) tot += ws[i];
        g_nt[t] = tot;
    }
}

__global__ void offset_kernel() {
    int o = 0;
    for (int t = 0; t < T_; t++) { g_off[t] = o; o += g_nt[t]; }
    g_off[T_] = o;
}

__global__ void scatter_kernel(const int* __restrict__ lengths) {
    int idx = blockIdx.x * 256 + threadIdx.x;
    if (idx >= T_ * B_) return;
    int t = idx >> 7, b = idx & 127;
    if (lengths[b] > t) g_rowmap[g_off[t] + g_local[idx]] = idx;
}

// ---------------- converters ----------------
// W images: [whi | whi]  (weight duplicated; operand carries the split)
__global__ void convert_w_both(const float2* __restrict__ w_ih,
                               const float2* __restrict__ w_hh) {
    int idx = blockIdx.x * 256 + threadIdx.x;     // 2 * (2048*512)/2
    int half_sel = idx >= (G4H * 256);
    int i = idx - half_sel * (G4H * 256);
    const float2* w = half_sel ? w_hh : w_ih;
    __half* dst = half_sel ? g_Whh : g_Wih;
    int n = i >> 8, k2 = i & 255;
    float2 v = w[i];
    __half2 hi = __floats2half2_rn(v.x, v.y);
    __half2* base = (__half2*)(dst + (size_t)n * K2_ + 2 * k2);
    base[0] = hi; base[256] = hi;
}

// X'' rows: [xhi | xlo]
__global__ void convert_x2(const float* __restrict__ features,
                           const int*   __restrict__ captions,
                           const float* __restrict__ embed_w) {
    int idx = blockIdx.x * 256 + threadIdx.x;     // (2560*512)/2
    int r = idx >> 8, k2 = idx & 255;
    int t = r >> 7, b = r & 127;
    float2 v;
    if (t == 0) v = ((const float2*)features)[b * 256 + k2];
    else        v = ((const float2*)embed_w)[(size_t)captions[b * T_ + (t - 1)] * 256 + k2];
    __half2 hi = __floats2half2_rn(v.x, v.y);
    __half2 lo = __floats2half2_rn(v.x - __low2float(hi), v.y - __high2float(hi));
    __half2* base = (__half2*)(g_X2 + (size_t)r * K2_ + 2 * k2);
    base[0] = hi; base[256] = lo;
}

__global__ void init_h2(const float* __restrict__ h0) {
    int idx = blockIdx.x * 256 + threadIdx.x;     // 128*512
    int b = idx >> 9, k = idx & 511;
    float v = h0[idx];
    __half hi = __float2half(v);
    __half lo = __float2half(v - __half2float(hi));
    size_t base = (size_t)b * K2_ + k;
    g_h2[0][base] = hi; g_h2[0][base + 512] = lo;
}

__global__ void convert_Bout(const float4* __restrict__ lin_w4) {
    int idx = blockIdx.x * 256 + threadIdx.x;
    float4 a = lin_w4[2 * idx], b = lin_w4[2 * idx + 1];
    __half2 h0 = __floats2half2_rn(a.x, a.y);
    __half2 h1 = __floats2half2_rn(a.z, a.w);
    __half2 h2 = __floats2half2_rn(b.x, b.y);
    __half2 h3 = __floats2half2_rn(b.z, b.w);
    uint4 o = {*(uint32_t*)&h0, *(uint32_t*)&h1, *(uint32_t*)&h2, *(uint32_t*)&h3};
    ((uint4*)g_Bh)[idx] = o;
}

__global__ void convert_Aout() {
    int idx = blockIdx.x * 256 + threadIdx.x;
    int m = idx >> 6, k8 = (idx & 63) * 8;
    int nr = g_off[T_];
    int src = (m < nr) ? g_rowmap[m] : 0;
    const float4* p = (const float4*)(g_hs + (size_t)src * 512 + k8);
    float4 a = p[0], b = p[1];
    __half2 h0 = __floats2half2_rn(a.x, a.y);
    __half2 h1 = __floats2half2_rn(a.z, a.w);
    __half2 h2 = __floats2half2_rn(b.x, b.y);
    __half2 h3 = __floats2half2_rn(b.z, b.w);
    uint4 o = {*(uint32_t*)&h0, *(uint32_t*)&h1, *(uint32_t*)&h2, *(uint32_t*)&h3};
    *(uint4*)(g_Ah + (size_t)m * 512 + k8) = o;
}

// ---------------- shared template constants ----------------
#define RS_      144
#define STAGE_   36864

// ---------------- gx GEMM: 2-stage, 2 CTAs/SM, K=1024 ----------------
__global__ void __launch_bounds__(256, 2) gx_mma(const float* __restrict__ b_ih,
                                                 const float* __restrict__ b_hh) {
    extern __shared__ char smem[];
    uint32_t sb = smem_u32(smem);
    int tid = threadIdx.x, lane = tid & 31, wid = tid >> 5;
    int n0 = blockIdx.x * 128, m0 = blockIdx.y * 128;
    int wm = (wid >> 2) * 64, wn = (wid & 3) * 32;
    float acc[4][4][4] = {};

#define GX_LOAD(s, kc) do { \
        uint32_t base_ = sb + (s) * STAGE_; \
        int k0_ = (kc) * 64; \
        for (int i = tid; i < 1024; i += 256) { \
            int r_ = i >> 3, c_ = i & 7; \
            cp_async16(base_ + r_ * RS_ + c_ * 16, \
                       g_X2 + (size_t)(m0 + r_) * K2_ + k0_ + c_ * 8); \
            cp_async16(base_ + 18432 + r_ * RS_ + c_ * 16, \
                       g_Wih + (size_t)(n0 + r_) * K2_ + k0_ + c_ * 8); \
        } \
        asm volatile("cp.async.commit_group;" ::: "memory"); \
    } while (0)

    GX_LOAD(0, 0);
    GX_LOAD(1, 1);
    for (int kc = 0; kc < 16; kc++) {
        asm volatile("cp.async.wait_group 1;" ::: "memory");
        __syncthreads();
        int s = kc & 1;
        uint32_t sA = sb + s * STAGE_;
        uint32_t sB = sA + 18432;
        uint32_t aA = sA + (uint32_t)(wm + (lane & 15)) * RS_ + ((lane >> 4) << 4);
        uint32_t aB = sB + (uint32_t)(wn + (lane & 7) + ((lane & 16) >> 1)) * RS_ + ((lane & 8) << 1);
#pragma unroll
        for (int st = 0; st < 4; st++) {
            uint32_t af[4][4], bfr[2][4];
#pragma unroll
            for (int ta = 0; ta < 4; ta++) ldsm_x4(af[ta], aA + ta * (16 * RS_) + st * 32);
#pragma unroll
            for (int tb = 0; tb < 2; tb++) ldsm_x4(bfr[tb], aB + tb * (16 * RS_) + st * 32);
#pragma unroll
            for (int ta = 0; ta < 4; ta++)
#pragma unroll
                for (int tn = 0; tn < 4; tn++)
                    mma_fp16(acc[ta][tn], af[ta], &bfr[tn >> 1][(tn & 1) * 2]);
        }
        __syncthreads();
        if (kc + 2 < 16) GX_LOAD(s, kc + 2);
        else asm volatile("cp.async.commit_group;" ::: "memory");
    }
#undef GX_LOAD

    int g = lane >> 2, tc2 = (lane & 3) * 2;
#pragma unroll
    for (int ta = 0; ta < 4; ta++) {
        int j0 = m0 + wm + ta * 16 + g;
#pragma unroll
        for (int tn = 0; tn < 4; tn++) {
            int col = n0 + wn + tn * 8 + tc2;
            float2 bi = {b_ih[col] + b_hh[col], b_ih[col + 1] + b_hh[col + 1]};
            float2 o0 = {acc[ta][tn][0] + bi.x, acc[ta][tn][1] + bi.y};
            float2 o1 = {acc[ta][tn][2] + bi.x, acc[ta][tn][3] + bi.y};
            *(float2*)&g_Gx[(size_t)j0 * G4H + col] = o0;
            *(float2*)&g_Gx[(size_t)(j0 + 8) * G4H + col] = o1;
        }
    }
}

// ---------------- recurrence GEMM (2-stage, K=1024, 2 chunks/split) ----------------
__global__ void __launch_bounds__(256, 1) rec_gemm(int t) {
    extern __shared__ char smem[];
    uint32_t sb = smem_u32(smem);
    int tid = threadIdx.x, lane = tid & 31, wid = tid >> 5;
    int split = blockIdx.x;
    int m0 = blockIdx.y * 128;
    const __half* hin = g_h2[t & 1];
    int wm = (wid >> 2) * 64, wn = (wid & 3) * 32;

    float acc[4][4][4] = {};

#define REC_LOAD(s, kc) do { \
        uint32_t base_ = sb + (s) * STAGE_; \
        int k0_ = (split * 2 + (kc)) * 64; \
        for (int i = tid; i < 1024; i += 256) { \
            int r_ = i >> 3, c_ = i & 7; \
            cp_async16(base_ + r_ * RS_ + c_ * 16, \
                       g_Whh + (size_t)(m0 + r_) * K2_ + k0_ + c_ * 8); \
            cp_async16(base_ + 18432 + r_ * RS_ + c_ * 16, \
                       hin + (size_t)r_ * K2_ + k0_ + c_ * 8); \
        } \
        asm volatile("cp.async.commit_group;" ::: "memory"); \
    } while (0)

    REC_LOAD(0, 0);
    REC_LOAD(1, 1);

    for (int kc = 0; kc < 2; kc++) {
        asm volatile("cp.async.wait_group 1;" ::: "memory");
        __syncthreads();
        int s = kc & 1;
        uint32_t sA = sb + s * STAGE_;
        uint32_t sB = sA + 18432;
        uint32_t aA = sA + (uint32_t)(wm + (lane & 15)) * RS_ + ((lane >> 4) << 4);
        uint32_t aB = sB + (uint32_t)(wn + (lane & 7) + ((lane & 16) >> 1)) * RS_ + ((lane & 8) << 1);
#pragma unroll
        for (int st = 0; st < 4; st++) {
            uint32_t af[4][4], bfr[2][4];
#pragma unroll
            for (int ta = 0; ta < 4; ta++) ldsm_x4(af[ta], aA + ta * (16 * RS_) + st * 32);
#pragma unroll
            for (int tb = 0; tb < 2; tb++) ldsm_x4(bfr[tb], aB + tb * (16 * RS_) + st * 32);
#pragma unroll
            for (int ta = 0; ta < 4; ta++)
#pragma unroll
                for (int tn = 0; tn < 4; tn++)
                    mma_fp16(acc[ta][tn], af[ta], &bfr[tn >> 1][(tn & 1) * 2]);
        }
        __syncthreads();
        asm volatile("cp.async.commit_group;" ::: "memory");
    }
#undef REC_LOAD

    float* part = g_part + (size_t)split * G4H * B_;
    int g = lane >> 2, tc2 = (lane & 3) * 2;
#pragma unroll
    for (int ta = 0; ta < 4; ta++) {
        int j0 = m0 + wm + ta * 16 + g;
        int j1 = j0 + 8;
#pragma unroll
        for (int tn = 0; tn < 4; tn++) {
            int col = wn + tn * 8 + tc2;
            float2 o0 = {acc[ta][tn][0], acc[ta][tn][1]};
            float2 o1 = {acc[ta][tn][2], acc[ta][tn][3]};
            *(float2*)&part[(size_t)j0 * B_ + col] = o0;
            *(float2*)&part[(size_t)j1 * B_ + col] = o1;
        }
    }
}

// ---------------- cell + split reduce + h'' emit ----------------
__device__ __forceinline__ float sigmoidf_(float x) { return 1.0f / (1.0f + expf(-x)); }

__global__ void cell_reduce(int t, const float* __restrict__ c0) {
    int idx = blockIdx.x * 256 + threadIdx.x;
    int b = idx & 127, j = idx >> 7;
    const float* gxr = g_Gx + (size_t)(t * B_ + b) * G4H;
    __half* hout = g_h2[(t + 1) & 1];

    float gate[4];
#pragma unroll
    for (int g = 0; g < 4; g++) {
        float s = gxr[g * 512 + j];
        size_t off = (size_t)(g * 512 + j) * B_ + b;
#pragma unroll
        for (int sp = 0; sp < NSPLIT; sp++)
            s += g_part[(size_t)sp * G4H * B_ + off];
        gate[g] = s;
    }
    float cp = (t == 0) ? c0[b * 512 + j] : g_c[j * 128 + b];
    float cn = sigmoidf_(gate[1]) * cp + sigmoidf_(gate[0]) * tanhf(gate[2]);
    float h = sigmoidf_(gate[3]) * tanhf(cn);
    g_c[j * 128 + b] = cn;
    g_hs[(size_t)t * B_ * H_ + b * 512 + j] = h;
    __half hh = __float2half(h);
    __half hl = __float2half(h - __half2float(hh));
    size_t hb = (size_t)b * K2_ + j;
    hout[hb] = hh; hout[hb + 512] = hl;
}

// ---------------- out GEMM: 2-stage, 2 CTAs/SM (proven R13) ----------------
#define NCHUNK_  8

__global__ void __launch_bounds__(256, 2) out_gemm_mma(const float* __restrict__ lin_b,
                                                       float* __restrict__ out, int nrows) {
    extern __shared__ char smem[];
    uint32_t sb = smem_u32(smem);
    int tid = threadIdx.x, lane = tid & 31, wid = tid >> 5;
    int n0 = blockIdx.x * 128, m0 = blockIdx.y * 128;
    int wm = (wid >> 2) * 64, wn = (wid & 3) * 32;

    float acc[4][4][4] = {};

#define LOAD_STAGE(s, kc) do { \
        uint32_t base_ = sb + (s) * STAGE_; \
        int k0_ = (kc) * 64; \
        for (int i = tid; i < 1024; i += 256) { \
            int r_ = i >> 3, c_ = i & 7; \
            cp_async16(base_ + r_ * RS_ + c_ * 16, \
                       g_Ah + (size_t)(m0 + r_) * 512 + k0_ + c_ * 8); \
            cp_async16(base_ + 18432 + r_ * RS_ + c_ * 16, \
                       g_Bh + (size_t)(n0 + r_) * 512 + k0_ + c_ * 8); \
        } \
        asm volatile("cp.async.commit_group;" ::: "memory"); \
    } while (0)

    LOAD_STAGE(0, 0);
    LOAD_STAGE(1, 1);

    for (int kc = 0; kc < NCHUNK_; kc++) {
        asm volatile("cp.async.wait_group 1;" ::: "memory");
        __syncthreads();
        int s = kc & 1;
        uint32_t sA = sb + s * STAGE_;
        uint32_t sB = sA + 18432;
        uint32_t aA = sA + (uint32_t)(wm + (lane & 15)) * RS_ + ((lane >> 4) << 4);
        uint32_t aB = sB + (uint32_t)(wn + (lane & 7) + ((lane & 16) >> 1)) * RS_ + ((lane & 8) << 1);
#pragma unroll
        for (int st = 0; st < 4; st++) {
            uint32_t af[4][4], bfr[2][4];
#pragma unroll
            for (int ta = 0; ta < 4; ta++) ldsm_x4(af[ta], aA + ta * (16 * RS_) + st * 32);
#pragma unroll
            for (int tb = 0; tb < 2; tb++) ldsm_x4(bfr[tb], aB + tb * (16 * RS_) + st * 32);
#pragma unroll
            for (int ta = 0; ta < 4; ta++)
#pragma unroll
                for (int tn = 0; tn < 4; tn++)
                    mma_fp16(acc[ta][tn], af[ta], &bfr[tn >> 1][(tn & 1) * 2]);
        }
        __syncthreads();
        if (kc + 2 < NCHUNK_) {
            LOAD_STAGE(s, kc + 2);
        } else {
            asm volatile("cp.async.commit_group;" ::: "memory");
        }
    }
#undef LOAD_STAGE

    int g = lane >> 2, tc2 = (lane & 3) * 2;
#pragma unroll
    for (int ta = 0; ta < 4; ta++) {
        int j0 = m0 + wm + ta * 16 + g;
        int j1 = j0 + 8;
#pragma unroll
        for (int tn = 0; tn < 4; tn++) {
            int col = n0 + wn + tn * 8 + tc2;
            float2 lb = *(const float2*)&lin_b[col];
            if (j0 < nrows) {
                float2 o = {acc[ta][tn][0] + lb.x, acc[ta][tn][1] + lb.y};
                *(float2*)&out[(size_t)j0 * V_ + col] = o;
            }
            if (j1 < nrows) {
                float2 o = {acc[ta][tn][2] + lb.x, acc[ta][tn][3] + lb.y};
                *(float2*)&out[(size_t)j1 * V_ + col] = o;
            }
        }
    }
}

// ---------------- launch ----------------
extern "C" void kernel_launch(void* const* d_in, const int* in_sizes, int n_in,
                              void* d_out, int out_size) {
    const float* features = (const float*)d_in[0];
    const int*   captions = (const int*)d_in[1];
    const int*   lengths  = (const int*)d_in[2];
    const float* h0       = (const float*)d_in[3];
    const float* c0       = (const float*)d_in[4];
    const float* embed_w  = (const float*)d_in[5];
    const float* w_ih     = (const float*)d_in[6];
    const float* w_hh     = (const float*)d_in[7];
    const float* b_ih     = (const float*)d_in[8];
    const float* b_hh     = (const float*)d_in[9];
    const float* lin_w    = (const float*)d_in[10];
    const float* lin_b    = (const float*)d_in[11];
    float* out = (float*)d_out;
    int nrows = out_size / V_;

    cudaFuncSetAttribute(out_gemm_mma, cudaFuncAttributeMaxDynamicSharedMemorySize,
                         2 * STAGE_);
    cudaFuncSetAttribute(gx_mma, cudaFuncAttributeMaxDynamicSharedMemorySize,
                         2 * STAGE_);
    cudaFuncSetAttribute(rec_gemm, cudaFuncAttributeMaxDynamicSharedMemorySize,
                         2 * STAGE_);

    // pack indices
    count_kernel<<<T_, 128>>>(lengths);
    offset_kernel<<<1, 1>>>();
    scatter_kernel<<<(T_ * B_ + 255) / 256, 256>>>(lengths);

    // operand builds
    convert_Bout<<<(V_ * 512 / 8) / 256, 256>>>((const float4*)lin_w);
    convert_w_both<<<(2 * G4H * 512 / 2) / 256, 256>>>((const float2*)w_ih,
                                                       (const float2*)w_hh);
    convert_x2<<<(2560 * 512 / 2) / 256, 256>>>(features, captions, embed_w);
    init_h2<<<(B_ * 512) / 256, 256>>>(h0);

    // input projection (K=1024)
    gx_mma<<<dim3(G4H / 128, 2560 / 128), 256, 2 * STAGE_>>>(b_ih, b_hh);

    // recurrence (per-step launches, K=1024)
    for (int t = 0; t < T_; t++) {
        rec_gemm<<<dim3(NSPLIT, G4H / 128), 256, 2 * STAGE_>>>(t);
        cell_reduce<<<(B_ * H_) / 256, 256>>>(t, c0);
    }

    // A operand build
    convert_Aout<<<(1664 * 512 / 8) / 256, 256>>>();

    // logits GEMM
    int mtiles = (nrows + 127) / 128;   // 13
    out_gemm_mma<<<dim3(V_ / 128, mtiles), 256, 2 * STAGE_>>>(lin_b, out, nrows);
}

// round 17
// speedup vs baseline: 4.0658x; 1.1019x over previous
#include <cuda_runtime.h>
#include <cuda_fp16.h>
#include <math.h>
#include <cstdint>

#define B_   128
#define T_   20
#define E_   512
#define H_   512
#define V_   32000
#define G4H  2048   // 4*H
#define NSPLIT 8

// ---------------- scratch (static device globals; IN-KERNEL access only) ----------------
__device__ float g_Gx[T_ * B_ * G4H];
__device__ float g_hs[T_ * B_ * H_];
__device__ float g_c[B_ * H_];
__device__ float g_part[NSPLIT * G4H * B_];
__device__ int   g_nt[T_];
__device__ int   g_off[T_ + 1];
__device__ int   g_local[T_ * B_];
__device__ int   g_rowmap[T_ * B_];

__device__ __align__(16) __half g_X2[2560u * 512u];    // plain fp16 X
__device__ __align__(16) __half g_Wih[G4H * 512u];     // plain fp16
__device__ __align__(16) __half g_Whh[G4H * 512u];     // plain fp16
__device__ __align__(16) __half g_h2[2][B_ * 512u];    // ping-pong plain fp16 h
__device__ __align__(16) __half g_Ah[1664u * 512u];
__device__ __align__(16) __half g_Bh[32000u * 512u];

// ---------------- PTX helpers ----------------
__device__ __forceinline__ uint32_t smem_u32(const void* p) {
    uint32_t a;
    asm("{ .reg .u64 t; cvta.to.shared.u64 t, %1; cvt.u32.u64 %0, t; }" : "=r"(a) : "l"(p));
    return a;
}
__device__ __forceinline__ void cp_async16(uint32_t saddr, const void* g) {
    asm volatile("cp.async.cg.shared.global [%0], [%1], 16;" :: "r"(saddr), "l"(g));
}
__device__ __forceinline__ void ldsm_x4(uint32_t* r, uint32_t addr) {
    asm volatile("ldmatrix.sync.aligned.m8n8.x4.shared.b16 {%0,%1,%2,%3}, [%4];"
        : "=r"(r[0]), "=r"(r[1]), "=r"(r[2]), "=r"(r[3]) : "r"(addr));
}
__device__ __forceinline__ void mma_fp16(float* d, const uint32_t* a, const uint32_t* b) {
    asm volatile("mma.sync.aligned.m16n8k16.row.col.f32.f16.f16.f32 "
        "{%0,%1,%2,%3}, {%4,%5,%6,%7}, {%8,%9}, {%0,%1,%2,%3};"
        : "+f"(d[0]), "+f"(d[1]), "+f"(d[2]), "+f"(d[3])
        : "r"(a[0]), "r"(a[1]), "r"(a[2]), "r"(a[3]), "r"(b[0]), "r"(b[1]));
}

// ---------------- pack-index machinery ----------------
__global__ void count_kernel(const int* __restrict__ lengths) {
    int t = blockIdx.x, b = threadIdx.x;
    int pred = lengths[b] > t;
    unsigned m = __ballot_sync(0xffffffffu, pred);
    int lane = b & 31, w = b >> 5;
    __shared__ int ws[4];
    if (lane == 0) ws[w] = __popc(m);
    __syncthreads();
    int prefix = 0;
#pragma unroll
    for (int i = 0; i < 4; i++) if (i < w) prefix += ws[i];
    g_local[t * B_ + b] = prefix + __popc(m & ((1u << lane) - 1u));
    if (b == 0) {
        int tot = 0;
#pragma unroll
        for (int i = 0; i < 4; i++) tot += ws[i];
        g_nt[t] = tot;
    }
}

__global__ void offset_kernel() {
    int o = 0;
    for (int t = 0; t < T_; t++) { g_off[t] = o; o += g_nt[t]; }
    g_off[T_] = o;
}

__global__ void scatter_kernel(const int* __restrict__ lengths) {
    int idx = blockIdx.x * 256 + threadIdx.x;
    if (idx >= T_ * B_) return;
    int t = idx >> 7, b = idx & 127;
    if (lengths[b] > t) g_rowmap[g_off[t] + g_local[idx]] = idx;
}

// ---------------- converters (plain fp16, vectorized 8-wide) ----------------
__device__ __forceinline__ uint4 cvt8(float4 a, float4 b) {
    __half2 h0 = __floats2half2_rn(a.x, a.y);
    __half2 h1 = __floats2half2_rn(a.z, a.w);
    __half2 h2 = __floats2half2_rn(b.x, b.y);
    __half2 h3 = __floats2half2_rn(b.z, b.w);
    uint4 o = {*(uint32_t*)&h0, *(uint32_t*)&h1, *(uint32_t*)&h2, *(uint32_t*)&h3};
    return o;
}

__global__ void convert_w_both(const float4* __restrict__ w_ih,
                               const float4* __restrict__ w_hh) {
    int idx = blockIdx.x * 256 + threadIdx.x;     // 2 * (2048*512)/8
    int half_sel = idx >= (G4H * 64);
    int i = idx - half_sel * (G4H * 64);
    const float4* w = half_sel ? w_hh : w_ih;
    __half* dst = half_sel ? g_Whh : g_Wih;
    ((uint4*)dst)[i] = cvt8(w[2 * i], w[2 * i + 1]);
}

__global__ void convert_x2(const float* __restrict__ features,
                           const int*   __restrict__ captions,
                           const float* __restrict__ embed_w) {
    int idx = blockIdx.x * 256 + threadIdx.x;     // (2560*512)/8
    int r = idx >> 6, k8 = (idx & 63) * 8;
    int t = r >> 7, b = r & 127;
    const float4* src;
    if (t == 0) src = (const float4*)(features + (size_t)b * E_ + k8);
    else        src = (const float4*)(embed_w + (size_t)captions[b * T_ + (t - 1)] * E_ + k8);
    ((uint4*)g_X2)[idx] = cvt8(src[0], src[1]);
}

__global__ void init_h2(const float* __restrict__ h0) {
    int idx = blockIdx.x * 256 + threadIdx.x;     // (128*512)/8
    const float4* src = (const float4*)(h0 + idx * 8);
    ((uint4*)g_h2[0])[idx] = cvt8(src[0], src[1]);
}

__global__ void convert_Bout(const float4* __restrict__ lin_w4) {
    int idx = blockIdx.x * 256 + threadIdx.x;
    ((uint4*)g_Bh)[idx] = cvt8(lin_w4[2 * idx], lin_w4[2 * idx + 1]);
}

__global__ void convert_Aout() {
    int idx = blockIdx.x * 256 + threadIdx.x;
    int m = idx >> 6, k8 = (idx & 63) * 8;
    int nr = g_off[T_];
    int src = (m < nr) ? g_rowmap[m] : 0;
    const float4* p = (const float4*)(g_hs + (size_t)src * 512 + k8);
    *(uint4*)(g_Ah + (size_t)m * 512 + k8) = cvt8(p[0], p[1]);
}

// ---------------- shared template constants ----------------
#define RS_      144
#define STAGE_   36864

// ---------------- gx GEMM: 2-stage, 2 CTAs/SM, K=512 ----------------
__global__ void __launch_bounds__(256, 2) gx_mma(const float* __restrict__ b_ih,
                                                 const float* __restrict__ b_hh) {
    extern __shared__ char smem[];
    uint32_t sb = smem_u32(smem);
    int tid = threadIdx.x, lane = tid & 31, wid = tid >> 5;
    int n0 = blockIdx.x * 128, m0 = blockIdx.y * 128;
    int wm = (wid >> 2) * 64, wn = (wid & 3) * 32;
    float acc[4][4][4] = {};

#define GX_LOAD(s, kc) do { \
        uint32_t base_ = sb + (s) * STAGE_; \
        int k0_ = (kc) * 64; \
        for (int i = tid; i < 1024; i += 256) { \
            int r_ = i >> 3, c_ = i & 7; \
            cp_async16(base_ + r_ * RS_ + c_ * 16, \
                       g_X2 + (size_t)(m0 + r_) * 512 + k0_ + c_ * 8); \
            cp_async16(base_ + 18432 + r_ * RS_ + c_ * 16, \
                       g_Wih + (size_t)(n0 + r_) * 512 + k0_ + c_ * 8); \
        } \
        asm volatile("cp.async.commit_group;" ::: "memory"); \
    } while (0)

    GX_LOAD(0, 0);
    GX_LOAD(1, 1);
    for (int kc = 0; kc < 8; kc++) {
        asm volatile("cp.async.wait_group 1;" ::: "memory");
        __syncthreads();
        int s = kc & 1;
        uint32_t sA = sb + s * STAGE_;
        uint32_t sB = sA + 18432;
        uint32_t aA = sA + (uint32_t)(wm + (lane & 15)) * RS_ + ((lane >> 4) << 4);
        uint32_t aB = sB + (uint32_t)(wn + (lane & 7) + ((lane & 16) >> 1)) * RS_ + ((lane & 8) << 1);
#pragma unroll
        for (int st = 0; st < 4; st++) {
            uint32_t af[4][4], bfr[2][4];
#pragma unroll
            for (int ta = 0; ta < 4; ta++) ldsm_x4(af[ta], aA + ta * (16 * RS_) + st * 32);
#pragma unroll
            for (int tb = 0; tb < 2; tb++) ldsm_x4(bfr[tb], aB + tb * (16 * RS_) + st * 32);
#pragma unroll
            for (int ta = 0; ta < 4; ta++)
#pragma unroll
                for (int tn = 0; tn < 4; tn++)
                    mma_fp16(acc[ta][tn], af[ta], &bfr[tn >> 1][(tn & 1) * 2]);
        }
        __syncthreads();
        if (kc + 2 < 8) GX_LOAD(s, kc + 2);
        else asm volatile("cp.async.commit_group;" ::: "memory");
    }
#undef GX_LOAD

    int g = lane >> 2, tc2 = (lane & 3) * 2;
#pragma unroll
    for (int ta = 0; ta < 4; ta++) {
        int j0 = m0 + wm + ta * 16 + g;
#pragma unroll
        for (int tn = 0; tn < 4; tn++) {
            int col = n0 + wn + tn * 8 + tc2;
            float2 bi = {b_ih[col] + b_hh[col], b_ih[col + 1] + b_hh[col + 1]};
            float2 o0 = {acc[ta][tn][0] + bi.x, acc[ta][tn][1] + bi.y};
            float2 o1 = {acc[ta][tn][2] + bi.x, acc[ta][tn][3] + bi.y};
            *(float2*)&g_Gx[(size_t)j0 * G4H + col] = o0;
            *(float2*)&g_Gx[(size_t)(j0 + 8) * G4H + col] = o1;
        }
    }
}

// ---------------- recurrence GEMM (single 64-chunk per split) ----------------
__global__ void __launch_bounds__(256, 1) rec_gemm(int t) {
    extern __shared__ char smem[];
    uint32_t sb = smem_u32(smem);
    int tid = threadIdx.x, lane = tid & 31, wid = tid >> 5;
    int split = blockIdx.x;
    int m0 = blockIdx.y * 128;
    const __half* hin = g_h2[t & 1];
    int wm = (wid >> 2) * 64, wn = (wid & 3) * 32;

    float acc[4][4][4] = {};

    // single stage: this split owns k in [split*64, split*64+64)
    {
        int k0_ = split * 64;
        for (int i = tid; i < 1024; i += 256) {
            int r_ = i >> 3, c_ = i & 7;
            cp_async16(sb + r_ * RS_ + c_ * 16,
                       g_Whh + (size_t)(m0 + r_) * 512 + k0_ + c_ * 8);
            cp_async16(sb + 18432 + r_ * RS_ + c_ * 16,
                       hin + (size_t)r_ * 512 + k0_ + c_ * 8);
        }
        asm volatile("cp.async.commit_group;" ::: "memory");
        asm volatile("cp.async.wait_group 0;" ::: "memory");
        __syncthreads();
    }
    {
        uint32_t sA = sb;
        uint32_t sB = sA + 18432;
        uint32_t aA = sA + (uint32_t)(wm + (lane & 15)) * RS_ + ((lane >> 4) << 4);
        uint32_t aB = sB + (uint32_t)(wn + (lane & 7) + ((lane & 16) >> 1)) * RS_ + ((lane & 8) << 1);
#pragma unroll
        for (int st = 0; st < 4; st++) {
            uint32_t af[4][4], bfr[2][4];
#pragma unroll
            for (int ta = 0; ta < 4; ta++) ldsm_x4(af[ta], aA + ta * (16 * RS_) + st * 32);
#pragma unroll
            for (int tb = 0; tb < 2; tb++) ldsm_x4(bfr[tb], aB + tb * (16 * RS_) + st * 32);
#pragma unroll
            for (int ta = 0; ta < 4; ta++)
#pragma unroll
                for (int tn = 0; tn < 4; tn++)
                    mma_fp16(acc[ta][tn], af[ta], &bfr[tn >> 1][(tn & 1) * 2]);
        }
    }

    float* part = g_part + (size_t)split * G4H * B_;
    int g = lane >> 2, tc2 = (lane & 3) * 2;
#pragma unroll
    for (int ta = 0; ta < 4; ta++) {
        int j0 = m0 + wm + ta * 16 + g;
        int j1 = j0 + 8;
#pragma unroll
        for (int tn = 0; tn < 4; tn++) {
            int col = wn + tn * 8 + tc2;
            float2 o0 = {acc[ta][tn][0], acc[ta][tn][1]};
            float2 o1 = {acc[ta][tn][2], acc[ta][tn][3]};
            *(float2*)&part[(size_t)j0 * B_ + col] = o0;
            *(float2*)&part[(size_t)j1 * B_ + col] = o1;
        }
    }
}

// ---------------- cell + split reduce + h emit ----------------
__device__ __forceinline__ float sigmoidf_(float x) { return 1.0f / (1.0f + expf(-x)); }

__global__ void cell_reduce(int t, const float* __restrict__ c0) {
    int idx = blockIdx.x * 256 + threadIdx.x;
    int b = idx & 127, j = idx >> 7;
    const float* gxr = g_Gx + (size_t)(t * B_ + b) * G4H;
    __half* hout = g_h2[(t + 1) & 1];

    float gate[4];
#pragma unroll
    for (int g = 0; g < 4; g++) {
        float s = gxr[g * 512 + j];
        size_t off = (size_t)(g * 512 + j) * B_ + b;
#pragma unroll
        for (int sp = 0; sp < NSPLIT; sp++)
            s += g_part[(size_t)sp * G4H * B_ + off];
        gate[g] = s;
    }
    float cp = (t == 0) ? c0[b * 512 + j] : g_c[j * 128 + b];
    float cn = sigmoidf_(gate[1]) * cp + sigmoidf_(gate[0]) * tanhf(gate[2]);
    float h = sigmoidf_(gate[3]) * tanhf(cn);
    g_c[j * 128 + b] = cn;
    g_hs[(size_t)t * B_ * H_ + b * 512 + j] = h;
    hout[(size_t)b * 512 + j] = __float2half(h);
}

// ---------------- out GEMM: 2-stage, 2 CTAs/SM (proven R13) ----------------
#define NCHUNK_  8

__global__ void __launch_bounds__(256, 2) out_gemm_mma(const float* __restrict__ lin_b,
                                                       float* __restrict__ out, int nrows) {
    extern __shared__ char smem[];
    uint32_t sb = smem_u32(smem);
    int tid = threadIdx.x, lane = tid & 31, wid = tid >> 5;
    int n0 = blockIdx.x * 128, m0 = blockIdx.y * 128;
    int wm = (wid >> 2) * 64, wn = (wid & 3) * 32;

    float acc[4][4][4] = {};

#define LOAD_STAGE(s, kc) do { \
        uint32_t base_ = sb + (s) * STAGE_; \
        int k0_ = (kc) * 64; \
        for (int i = tid; i < 1024; i += 256) { \
            int r_ = i >> 3, c_ = i & 7; \
            cp_async16(base_ + r_ * RS_ + c_ * 16, \
                       g_Ah + (size_t)(m0 + r_) * 512 + k0_ + c_ * 8); \
            cp_async16(base_ + 18432 + r_ * RS_ + c_ * 16, \
                       g_Bh + (size_t)(n0 + r_) * 512 + k0_ + c_ * 8); \
        } \
        asm volatile("cp.async.commit_group;" ::: "memory"); \
    } while (0)

    LOAD_STAGE(0, 0);
    LOAD_STAGE(1, 1);

    for (int kc = 0; kc < NCHUNK_; kc++) {
        asm volatile("cp.async.wait_group 1;" ::: "memory");
        __syncthreads();
        int s = kc & 1;
        uint32_t sA = sb + s * STAGE_;
        uint32_t sB = sA + 18432;
        uint32_t aA = sA + (uint32_t)(wm + (lane & 15)) * RS_ + ((lane >> 4) << 4);
        uint32_t aB = sB + (uint32_t)(wn + (lane & 7) + ((lane & 16) >> 1)) * RS_ + ((lane & 8) << 1);
#pragma unroll
        for (int st = 0; st < 4; st++) {
            uint32_t af[4][4], bfr[2][4];
#pragma unroll
            for (int ta = 0; ta < 4; ta++) ldsm_x4(af[ta], aA + ta * (16 * RS_) + st * 32);
#pragma unroll
            for (int tb = 0; tb < 2; tb++) ldsm_x4(bfr[tb], aB + tb * (16 * RS_) + st * 32);
#pragma unroll
            for (int ta = 0; ta < 4; ta++)
#pragma unroll
                for (int tn = 0; tn < 4; tn++)
                    mma_fp16(acc[ta][tn], af[ta], &bfr[tn >> 1][(tn & 1) * 2]);
        }
        __syncthreads();
        if (kc + 2 < NCHUNK_) {
            LOAD_STAGE(s, kc + 2);
        } else {
            asm volatile("cp.async.commit_group;" ::: "memory");
        }
    }
#undef LOAD_STAGE

    int g = lane >> 2, tc2 = (lane & 3) * 2;
#pragma unroll
    for (int ta = 0; ta < 4; ta++) {
        int j0 = m0 + wm + ta * 16 + g;
        int j1 = j0 + 8;
#pragma unroll
        for (int tn = 0; tn < 4; tn++) {
            int col = n0 + wn + tn * 8 + tc2;
            float2 lb = *(const float2*)&lin_b[col];
            if (j0 < nrows) {
                float2 o = {acc[ta][tn][0] + lb.x, acc[ta][tn][1] + lb.y};
                *(float2*)&out[(size_t)j0 * V_ + col] = o;
            }
            if (j1 < nrows) {
                float2 o = {acc[ta][tn][2] + lb.x, acc[ta][tn][3] + lb.y};
                *(float2*)&out[(size_t)j1 * V_ + col] = o;
            }
        }
    }
}

// ---------------- launch ----------------
extern "C" void kernel_launch(void* const* d_in, const int* in_sizes, int n_in,
                              void* d_out, int out_size) {
    const float* features = (const float*)d_in[0];
    const int*   captions = (const int*)d_in[1];
    const int*   lengths  = (const int*)d_in[2];
    const float* h0       = (const float*)d_in[3];
    const float* c0       = (const float*)d_in[4];
    const float* embed_w  = (const float*)d_in[5];
    const float* w_ih     = (const float*)d_in[6];
    const float* w_hh     = (const float*)d_in[7];
    const float* b_ih     = (const float*)d_in[8];
    const float* b_hh     = (const float*)d_in[9];
    const float* lin_w    = (const float*)d_in[10];
    const float* lin_b    = (const float*)d_in[11];
    float* out = (float*)d_out;
    int nrows = out_size / V_;

    cudaFuncSetAttribute(out_gemm_mma, cudaFuncAttributeMaxDynamicSharedMemorySize,
                         2 * STAGE_);
    cudaFuncSetAttribute(gx_mma, cudaFuncAttributeMaxDynamicSharedMemorySize,
                         2 * STAGE_);
    cudaFuncSetAttribute(rec_gemm, cudaFuncAttributeMaxDynamicSharedMemorySize,
                         2 * STAGE_);

    // pack indices
    count_kernel<<<T_, 128>>>(lengths);
    offset_kernel<<<1, 1>>>();
    scatter_kernel<<<(T_ * B_ + 255) / 256, 256>>>(lengths);

    // operand builds (plain fp16)
    convert_Bout<<<(V_ * 512 / 8) / 256, 256>>>((const float4*)lin_w);
    convert_w_both<<<(2 * G4H * 512 / 8) / 256, 256>>>((const float4*)w_ih,
                                                       (const float4*)w_hh);
    convert_x2<<<(2560 * 512 / 8) / 256, 256>>>(features, captions, embed_w);
    init_h2<<<(B_ * 512 / 8) / 256, 256>>>(h0);

    // input projection (K=512)
    gx_mma<<<dim3(G4H / 128, 2560 / 128), 256, 2 * STAGE_>>>(b_ih, b_hh);

    // recurrence (per-step launches, single chunk per split)
    for (int t = 0; t < T_; t++) {
        rec_gemm<<<dim3(NSPLIT, G4H / 128), 256, 2 * STAGE_>>>(t);
        cell_reduce<<<(B_ * H_) / 256, 256>>>(t, c0);
    }

    // A operand build
    convert_Aout<<<(1664 * 512 / 8) / 256, 256>>>();

    // logits GEMM
    int mtiles = (nrows + 127) / 128;   // 13
    out_gemm_mma<<<dim3(V_ / 128, mtiles), 256, 2 * STAGE_>>>(lin_b, out, nrows);
}